// round 2
// baseline (speedup 1.0000x reference)
#include <cuda_runtime.h>
#include <math.h>

#define BN 8192
#define CN 128
#define NL 8
#define BC (BN*CN)
#define SLICE (BC*8)
#define AMU_SIZE (BN*32)
#define EPSF 1e-6f

// ------------------------- device scratch (no allocs allowed) -------------------------
__device__ float g_feats[BN*160];        // [B][160] padded features (cols 132..159 = 0)
__device__ float g_Wk[NL*8*CN*CN];       // repacked lin_W: [l][k][i][o]
__device__ float g_rotM[NL*CN*64];       // rotor sandwich matrices, [l][c][j][k]
__device__ float g_h[BC*8];              // lift output, interleaved [b][c][k]
__device__ float g_res[BC*8];            // residual, interleaved
__device__ float g_act[8*BC];            // blade-planar activations [k][b][i]
__device__ float g_gout[8*BC];           // blade-planar gemm output [k][b][o]

__device__ const int c_blades[8] = {0,1,2,4,3,5,6,7};   // blade bitmasks; also idx_of (involution)

__device__ __forceinline__ int cl_sign(int a, int b) {
    int s = 0; int aa = a >> 1;
    while (aa) { s += __popc(aa & b); aa >>= 1; }
    return (s & 1) ? -1 : 1;
}

// ------------------------- rotor matrix precompute -------------------------
// One thread per (layer, channel): M[j][k] such that (R x ~R)[k] = sum_j x[j] M[j*8+k]
__global__ void rotor_pre(const float* __restrict__ theta) {
    int n = blockIdx.x * blockDim.x + threadIdx.x;
    if (n >= NL * CN) return;
    const float* t = theta + n * 3;
    float ang = sqrtf(t[0]*t[0] + t[1]*t[1] + t[2]*t[2] + EPSF);
    float R[8] = {0,0,0,0,0,0,0,0};
    R[0] = cosf(ang);
    float s = sinf(ang) / ang;
    R[4] = s * t[0]; R[5] = s * t[1]; R[6] = s * t[2];
    float Rr[8];
    #pragma unroll
    for (int i = 0; i < 8; i++) Rr[i] = (i >= 4) ? -R[i] : R[i];

    float M[64];
    #pragma unroll
    for (int i = 0; i < 64; i++) M[i] = 0.0f;

    const int iv[4] = {0, 4, 5, 6};
    for (int ii = 0; ii < 4; ii++) {
        int i = iv[ii]; float Ri = R[i]; int a = c_blades[i];
        for (int j = 0; j < 8; j++) {
            int bb = c_blades[j];
            int m_mask = a ^ bb;
            float tj = Ri * (float)cl_sign(a, bb);
            for (int pp = 0; pp < 4; pp++) {
                int p = iv[pp]; int pm = c_blades[p];
                int k_mask = m_mask ^ pm;
                float s2 = (float)cl_sign(m_mask, pm);
                int k = c_blades[k_mask];            // idx_of == blades (involution)
                M[j*8 + k] += tj * Rr[p] * s2;
            }
        }
    }
    float* out = g_rotM + (size_t)n * 64;
    #pragma unroll
    for (int i = 0; i < 64; i++) out[i] = M[i];
}

// ------------------------- weight repack -------------------------
__global__ void repack(const float* __restrict__ linW) {
    int n = blockIdx.x * 256 + threadIdx.x;
    if (n >= NL*8*CN*CN) return;
    int o = n & 127;
    int i = (n >> 7) & 127;
    int k = (n >> 14) & 7;
    int l = n >> 17;
    g_Wk[n] = linW[(size_t)(((l*128 + o)*128 + i) * 8) + k];
}

// ------------------------- features -------------------------
__global__ void feats_kernel(const float* __restrict__ coords, const float* __restrict__ freq) {
    int gid = blockIdx.x * 256 + threadIdx.x;
    int row = gid >> 5, lane = gid & 31;
    if (row >= BN) return;
    float c0 = coords[row*4+0], c1 = coords[row*4+1];
    float c2 = coords[row*4+2], c3 = coords[row*4+3];
    float* out = g_feats + (size_t)row * 160;
    if (lane < 4) out[lane] = coords[row*4 + lane];
    #pragma unroll
    for (int f = lane; f < 64; f += 32) {
        float p = c0*freq[f] + c1*freq[64+f] + c2*freq[128+f] + c3*freq[192+f];
        out[4 + f]  = sinf(p);
        out[68 + f] = cosf(p);
    }
    if (lane < 28) out[132 + lane] = 0.0f;
}

// ------------------------- lift GEMM: [8192 x 132] x [132 x 1024] -------------------------
__global__ void __launch_bounds__(256) lift_gemm(const float* __restrict__ liftW,
                                                 const float* __restrict__ liftb) {
    __shared__ float As[32][136];
    __shared__ float Bs[32][136];
    int nb = blockIdx.x << 7, mb = blockIdx.y << 7;
    int tid = threadIdx.x;
    int tx = tid & 15, ty = tid >> 4;
    float acc[8][8];
    #pragma unroll
    for (int i = 0; i < 8; i++)
        #pragma unroll
        for (int j = 0; j < 8; j++) acc[i][j] = 0.0f;

    for (int kt = 0; kt < 160; kt += 32) {
        #pragma unroll
        for (int e = 0; e < 4; e++) {
            int q = tid*4 + e; int row = q >> 3, c4 = q & 7;
            float4 v = *(const float4*)(g_feats + (size_t)(mb + row)*160 + kt + c4*4);
            As[c4*4+0][row] = v.x; As[c4*4+1][row] = v.y;
            As[c4*4+2][row] = v.z; As[c4*4+3][row] = v.w;
        }
        #pragma unroll
        for (int e = 0; e < 4; e++) {
            int q = tid*4 + e; int r = q >> 5, c4 = q & 31;
            float4 v = make_float4(0.f, 0.f, 0.f, 0.f);
            if (kt + r < 132) v = *(const float4*)(liftW + (size_t)(kt + r)*1024 + nb + c4*4);
            *(float4*)&Bs[r][c4*4] = v;
        }
        __syncthreads();
        #pragma unroll
        for (int kk = 0; kk < 32; kk++) {
            float a[8], bv[8];
            *(float4*)(a)    = *(const float4*)&As[kk][ty*8];
            *(float4*)(a+4)  = *(const float4*)&As[kk][ty*8+4];
            *(float4*)(bv)   = *(const float4*)&Bs[kk][tx*8];
            *(float4*)(bv+4) = *(const float4*)&Bs[kk][tx*8+4];
            #pragma unroll
            for (int i = 0; i < 8; i++)
                #pragma unroll
                for (int j = 0; j < 8; j++)
                    acc[i][j] = fmaf(a[i], bv[j], acc[i][j]);
        }
        __syncthreads();
    }
    float bias[8];
    *(float4*)bias     = *(const float4*)(liftb + nb + tx*8);
    *(float4*)(bias+4) = *(const float4*)(liftb + nb + tx*8 + 4);
    #pragma unroll
    for (int i = 0; i < 8; i++) {
        int m = mb + ty*8 + i;
        float* op = g_h + (size_t)m*1024 + nb + tx*8;
        *(float4*)op     = make_float4(acc[i][0]+bias[0], acc[i][1]+bias[1],
                                       acc[i][2]+bias[2], acc[i][3]+bias[3]);
        *(float4*)(op+4) = make_float4(acc[i][4]+bias[4], acc[i][5]+bias[5],
                                       acc[i][6]+bias[6], acc[i][7]+bias[7]);
    }
}

// ------------------------- per-blade layer GEMM: gout[k][m][o] = act[k][m][:] . Wk[l][k][:][o] -------------------------
__global__ void __launch_bounds__(256) layer_gemm(int l) {
    __shared__ float As[32][136];
    __shared__ float Bs[32][136];
    int kb = blockIdx.x;
    int mb = blockIdx.y << 7;
    const float* __restrict__ A = g_act + (size_t)kb * BC;
    const float* __restrict__ W = g_Wk + (size_t)(l*8 + kb) * CN * CN;
    int tid = threadIdx.x;
    int tx = tid & 15, ty = tid >> 4;
    float acc[8][8];
    #pragma unroll
    for (int i = 0; i < 8; i++)
        #pragma unroll
        for (int j = 0; j < 8; j++) acc[i][j] = 0.0f;

    for (int kt = 0; kt < 128; kt += 32) {
        #pragma unroll
        for (int e = 0; e < 4; e++) {
            int q = tid*4 + e; int row = q >> 3, c4 = q & 7;
            float4 v = *(const float4*)(A + (size_t)(mb + row)*128 + kt + c4*4);
            As[c4*4+0][row] = v.x; As[c4*4+1][row] = v.y;
            As[c4*4+2][row] = v.z; As[c4*4+3][row] = v.w;
        }
        #pragma unroll
        for (int e = 0; e < 4; e++) {
            int q = tid*4 + e; int r = q >> 5, c4 = q & 31;
            float4 v = *(const float4*)(W + (size_t)(kt + r)*128 + c4*4);
            *(float4*)&Bs[r][c4*4] = v;
        }
        __syncthreads();
        #pragma unroll
        for (int kk = 0; kk < 32; kk++) {
            float a[8], bv[8];
            *(float4*)(a)    = *(const float4*)&As[kk][ty*8];
            *(float4*)(a+4)  = *(const float4*)&As[kk][ty*8+4];
            *(float4*)(bv)   = *(const float4*)&Bs[kk][tx*8];
            *(float4*)(bv+4) = *(const float4*)&Bs[kk][tx*8+4];
            #pragma unroll
            for (int i = 0; i < 8; i++)
                #pragma unroll
                for (int j = 0; j < 8; j++)
                    acc[i][j] = fmaf(a[i], bv[j], acc[i][j]);
        }
        __syncthreads();
    }
    #pragma unroll
    for (int i = 0; i < 8; i++) {
        float* op = g_gout + (size_t)kb*BC + (size_t)(mb + ty*8 + i)*128 + tx*8;
        *(float4*)op     = make_float4(acc[i][0], acc[i][1], acc[i][2], acc[i][3]);
        *(float4*)(op+4) = make_float4(acc[i][4], acc[i][5], acc[i][6], acc[i][7]);
    }
}

// ------------------------- grade-wise RMS block reduction (block = 128 threads = channels) ---------
__device__ __forceinline__ void grade_denom(const float* x, float* denom, float (*sred)[4], int tid) {
    float v[4];
    v[0] = x[0]*x[0];
    v[1] = x[1]*x[1] + x[2]*x[2] + x[3]*x[3];
    v[2] = x[4]*x[4] + x[5]*x[5] + x[6]*x[6];
    v[3] = x[7]*x[7];
    #pragma unroll
    for (int g = 0; g < 4; g++) {
        float t = v[g];
        t += __shfl_xor_sync(0xffffffffu, t, 16);
        t += __shfl_xor_sync(0xffffffffu, t, 8);
        t += __shfl_xor_sync(0xffffffffu, t, 4);
        t += __shfl_xor_sync(0xffffffffu, t, 2);
        t += __shfl_xor_sync(0xffffffffu, t, 1);
        if ((tid & 31) == 0) sred[g][tid >> 5] = t;
    }
    __syncthreads();
    #pragma unroll
    for (int g = 0; g < 4; g++)
        denom[g] = sqrtf((sred[g][0]+sred[g][1]+sred[g][2]+sred[g][3]) * (1.0f/128.0f) + EPSF);
    __syncthreads();   // allow sred reuse
}

__device__ __forceinline__ void ln_apply(float* x, const float* gamma, const float* denom, int c) {
    float f0 = gamma[c*4+0] / denom[0];
    float f1 = gamma[c*4+1] / denom[1];
    float f2 = gamma[c*4+2] / denom[2];
    float f3 = gamma[c*4+3] / denom[3];
    x[0] *= f0;
    x[1] *= f1; x[2] *= f1; x[3] *= f1;
    x[4] *= f2; x[5] *= f2; x[6] *= f2;
    x[7] *= f3;
}

__device__ __forceinline__ void rot_gelu_store(const float* x, const float* __restrict__ M,
                                               float alpha, int b, int c) {
    float y[8] = {0,0,0,0,0,0,0,0};
    #pragma unroll
    for (int j = 0; j < 8; j++) {
        float xj = x[j];
        #pragma unroll
        for (int k = 0; k < 8; k++) y[k] = fmaf(xj, M[j*8+k], y[k]);
    }
    float nn = EPSF;
    #pragma unroll
    for (int k = 0; k < 8; k++) nn = fmaf(y[k], y[k], nn);
    float gate = 0.5f * (1.0f + erff(alpha * sqrtf(nn) * 0.70710678118654752f));
    #pragma unroll
    for (int k = 0; k < 8; k++) g_act[(size_t)k*BC + b*128 + c] = y[k] * gate;
}

// ------------------------- input norm + layer-0 prologue -------------------------
__global__ void __launch_bounds__(128) ln_in_kernel(const float* __restrict__ in_gamma,
                                                    const float* __restrict__ ng0,
                                                    const float* __restrict__ alpha0) {
    __shared__ float sred[4][4];
    int b = blockIdx.x, c = threadIdx.x;
    float x[8];
    const float* p = g_h + (size_t)(b*128 + c) * 8;
    *(float4*)x     = *(const float4*)p;
    *(float4*)(x+4) = *(const float4*)(p+4);

    float denom[4];
    grade_denom(x, denom, sred, c);
    ln_apply(x, in_gamma, denom, c);

    float* pr = g_res + (size_t)(b*128 + c) * 8;
    *(float4*)pr     = *(const float4*)x;
    *(float4*)(pr+4) = *(const float4*)(x+4);

    grade_denom(x, denom, sred, c);
    ln_apply(x, ng0, denom, c);
    rot_gelu_store(x, g_rotM + (size_t)c*64, alpha0[c], b, c);
}

// ------------------------- inter-layer pointwise -------------------------
__global__ void __launch_bounds__(128) ip_kernel(int l, const float* __restrict__ linb,
                                                 float* __restrict__ outI,
                                                 const float* __restrict__ gamma_next,
                                                 const float* __restrict__ alpha_next,
                                                 int final_ln) {
    __shared__ float sred[4][4];
    int b = blockIdx.x, c = threadIdx.x;
    float x[8];
    #pragma unroll
    for (int k = 0; k < 8; k++)
        x[k] = g_gout[(size_t)k*BC + b*128 + c] + linb[c*8 + k];

    const float* pr = g_res + (size_t)(b*128 + c) * 8;
    float r[8];
    *(float4*)r     = *(const float4*)pr;
    *(float4*)(r+4) = *(const float4*)(pr+4);
    #pragma unroll
    for (int k = 0; k < 8; k++) x[k] += r[k];

    float* po = outI + (size_t)(b*128 + c) * 8;
    *(float4*)po     = *(const float4*)x;
    *(float4*)(po+4) = *(const float4*)(x+4);
    float* ps = g_res + (size_t)(b*128 + c) * 8;
    *(float4*)ps     = *(const float4*)x;
    *(float4*)(ps+4) = *(const float4*)(x+4);

    float denom[4];
    grade_denom(x, denom, sred, c);
    ln_apply(x, gamma_next, denom, c);

    if (!final_ln) {
        rot_gelu_store(x, g_rotM + (size_t)((l+1)*128 + c)*64, alpha_next[c], b, c);
    } else {
        #pragma unroll
        for (int k = 0; k < 8; k++) g_act[(size_t)k*BC + b*128 + c] = x[k];
    }
}

// ------------------------- projection (bivector blades only) -------------------------
__global__ void __launch_bounds__(256) proj_kernel(const float* __restrict__ projW,
                                                   const float* __restrict__ projb,
                                                   float* __restrict__ out) {
    int warp = threadIdx.x >> 5, lane = threadIdx.x & 31;
    int b = blockIdx.x * 8 + warp;
    if (b >= BN) return;

    out[b*32 + lane] = 0.0f;   // zero all 32 outputs first (bivector mask)
    __syncwarp();

    #pragma unroll
    for (int kk = 0; kk < 3; kk++) {
        int k = 4 + kk;
        float av[4];
        #pragma unroll
        for (int q = 0; q < 4; q++)
            av[q] = g_act[(size_t)k*BC + b*128 + lane + 32*q];
        #pragma unroll
        for (int o = 0; o < 4; o++) {
            float s = 0.0f;
            #pragma unroll
            for (int q = 0; q < 4; q++)
                s = fmaf(av[q], projW[(size_t)(o*128 + lane + 32*q)*8 + k], s);
            s += __shfl_xor_sync(0xffffffffu, s, 16);
            s += __shfl_xor_sync(0xffffffffu, s, 8);
            s += __shfl_xor_sync(0xffffffffu, s, 4);
            s += __shfl_xor_sync(0xffffffffu, s, 2);
            s += __shfl_xor_sync(0xffffffffu, s, 1);
            if (lane == 0) out[b*32 + o*8 + k] = s + projb[o*8 + k];
        }
    }
}

// ------------------------- launch -------------------------
extern "C" void kernel_launch(void* const* d_in, const int* in_sizes, int n_in,
                              void* d_out, int out_size) {
    const float* coords     = (const float*)d_in[0];
    const float* freq       = (const float*)d_in[1];
    const float* liftW      = (const float*)d_in[2];
    const float* liftb      = (const float*)d_in[3];
    const float* in_gamma   = (const float*)d_in[4];
    const float* norm_gamma = (const float*)d_in[5];
    const float* rotor_th   = (const float*)d_in[6];
    const float* act_alpha  = (const float*)d_in[7];
    const float* linW       = (const float*)d_in[8];
    const float* linb       = (const float*)d_in[9];
    const float* out_gamma  = (const float*)d_in[10];
    const float* projW      = (const float*)d_in[11];
    const float* projb      = (const float*)d_in[12];
    float* out = (float*)d_out;

    repack<<<(NL*8*CN*CN + 255)/256, 256>>>(linW);
    rotor_pre<<<4, 256>>>(rotor_th);
    feats_kernel<<<BN*32/256, 256>>>(coords, freq);
    lift_gemm<<<dim3(8, BN/128), 256>>>(liftW, liftb);
    ln_in_kernel<<<BN, 128>>>(in_gamma, norm_gamma, act_alpha);

    for (int l = 0; l < NL; l++) {
        layer_gemm<<<dim3(8, BN/128), 256>>>(l);
        const float* gnext = (l < NL-1) ? (norm_gamma + (size_t)(l+1)*CN*4) : out_gamma;
        const float* anext = (l < NL-1) ? (act_alpha + (size_t)(l+1)*CN)   : act_alpha;
        ip_kernel<<<BN, 128>>>(l, linb + (size_t)l*CN*8,
                               out + AMU_SIZE + (size_t)l*SLICE,
                               gnext, anext, (l == NL-1) ? 1 : 0);
    }
    proj_kernel<<<BN/8, 256>>>(projW, projb, out);
}

// round 3
// speedup vs baseline: 2.8620x; 2.8620x over previous
#include <cuda_runtime.h>
#include <math.h>

#define BN 8192
#define CN 128
#define NL 8
#define BC (BN*CN)
#define SLICE (BC*8)
#define AMU_SIZE (BN*32)
#define EPSF 1e-6f

// ------------------------- device scratch (no allocs allowed) -------------------------
__device__ float g_feats[BN*160];        // [B][160] padded features (cols 132..159 = 0)
__device__ float g_Wk[NL*8*CN*CN];       // repacked lin_W: [l][k][i][o]
__device__ float g_rotM[NL*64*CN];       // rotor matrices TRANSPOSED: [l][j*8+k][c]
__device__ float g_h[BC*8];              // lift output, interleaved [b][c][k]
__device__ float g_res[BC*8];            // residual for layer 0 only
__device__ float g_act[8*BC];            // blade-planar activations [k][b][i]
__device__ float g_gout[8*BC];           // blade-planar gemm output [k][b][o]

__device__ const int c_blades[8] = {0,1,2,4,3,5,6,7};   // blade bitmasks; idx_of == blades

__device__ __forceinline__ int cl_sign(int a, int b) {
    int s = 0; int aa = a >> 1;
    while (aa) { s += __popc(aa & b); aa >>= 1; }
    return (s & 1) ? -1 : 1;
}

// ------------------------- rotor matrix precompute (transposed store) -------------------------
__global__ void rotor_pre(const float* __restrict__ theta) {
    int n = blockIdx.x * blockDim.x + threadIdx.x;
    if (n >= NL * CN) return;
    int l = n / CN, c = n % CN;
    const float* t = theta + n * 3;
    float ang = sqrtf(t[0]*t[0] + t[1]*t[1] + t[2]*t[2] + EPSF);
    float R[8] = {0,0,0,0,0,0,0,0};
    R[0] = cosf(ang);
    float s = sinf(ang) / ang;
    R[4] = s * t[0]; R[5] = s * t[1]; R[6] = s * t[2];
    float Rr[8];
    #pragma unroll
    for (int i = 0; i < 8; i++) Rr[i] = (i >= 4) ? -R[i] : R[i];

    float M[64];
    #pragma unroll
    for (int i = 0; i < 64; i++) M[i] = 0.0f;

    const int iv[4] = {0, 4, 5, 6};
    for (int ii = 0; ii < 4; ii++) {
        int i = iv[ii]; float Ri = R[i]; int a = c_blades[i];
        for (int j = 0; j < 8; j++) {
            int bb = c_blades[j];
            int m_mask = a ^ bb;
            float tj = Ri * (float)cl_sign(a, bb);
            for (int pp = 0; pp < 4; pp++) {
                int p = iv[pp]; int pm = c_blades[p];
                int k_mask = m_mask ^ pm;
                float s2 = (float)cl_sign(m_mask, pm);
                int k = c_blades[k_mask];
                M[j*8 + k] += tj * Rr[p] * s2;
            }
        }
    }
    // transposed: [l][jk][c]
    float* out = g_rotM + (size_t)l*64*CN + c;
    #pragma unroll
    for (int i = 0; i < 64; i++) out[(size_t)i*CN] = M[i];
}

// ------------------------- weight repack -------------------------
__global__ void repack(const float* __restrict__ linW) {
    int n = blockIdx.x * 256 + threadIdx.x;
    if (n >= NL*8*CN*CN) return;
    int o = n & 127;
    int i = (n >> 7) & 127;
    int k = (n >> 14) & 7;
    int l = n >> 17;
    g_Wk[n] = linW[(size_t)(((l*128 + o)*128 + i) * 8) + k];
}

// ------------------------- features -------------------------
__global__ void feats_kernel(const float* __restrict__ coords, const float* __restrict__ freq) {
    int gid = blockIdx.x * 256 + threadIdx.x;
    int row = gid >> 5, lane = gid & 31;
    if (row >= BN) return;
    float c0 = coords[row*4+0], c1 = coords[row*4+1];
    float c2 = coords[row*4+2], c3 = coords[row*4+3];
    float* out = g_feats + (size_t)row * 160;
    if (lane < 4) out[lane] = coords[row*4 + lane];
    #pragma unroll
    for (int f = lane; f < 64; f += 32) {
        float p = c0*freq[f] + c1*freq[64+f] + c2*freq[128+f] + c3*freq[192+f];
        out[4 + f]  = sinf(p);
        out[68 + f] = cosf(p);
    }
    if (lane < 28) out[132 + lane] = 0.0f;
}

// ------------------------- lift GEMM: [8192 x 132] x [132 x 1024] -------------------------
__global__ void __launch_bounds__(256) lift_gemm(const float* __restrict__ liftW,
                                                 const float* __restrict__ liftb) {
    __shared__ float As[32][136];
    __shared__ float Bs[32][136];
    int nb = blockIdx.x << 7, mb = blockIdx.y << 7;
    int tid = threadIdx.x;
    int tx = tid & 15, ty = tid >> 4;
    float acc[8][8];
    #pragma unroll
    for (int i = 0; i < 8; i++)
        #pragma unroll
        for (int j = 0; j < 8; j++) acc[i][j] = 0.0f;

    for (int kt = 0; kt < 160; kt += 32) {
        #pragma unroll
        for (int e = 0; e < 4; e++) {
            int q = tid*4 + e; int row = q >> 3, c4 = q & 7;
            float4 v = *(const float4*)(g_feats + (size_t)(mb + row)*160 + kt + c4*4);
            As[c4*4+0][row] = v.x; As[c4*4+1][row] = v.y;
            As[c4*4+2][row] = v.z; As[c4*4+3][row] = v.w;
        }
        #pragma unroll
        for (int e = 0; e < 4; e++) {
            int q = tid*4 + e; int r = q >> 5, c4 = q & 31;
            float4 v = make_float4(0.f, 0.f, 0.f, 0.f);
            if (kt + r < 132) v = *(const float4*)(liftW + (size_t)(kt + r)*1024 + nb + c4*4);
            *(float4*)&Bs[r][c4*4] = v;
        }
        __syncthreads();
        #pragma unroll
        for (int kk = 0; kk < 32; kk++) {
            float a[8], bv[8];
            *(float4*)(a)    = *(const float4*)&As[kk][ty*8];
            *(float4*)(a+4)  = *(const float4*)&As[kk][ty*8+4];
            *(float4*)(bv)   = *(const float4*)&Bs[kk][tx*8];
            *(float4*)(bv+4) = *(const float4*)&Bs[kk][tx*8+4];
            #pragma unroll
            for (int i = 0; i < 8; i++)
                #pragma unroll
                for (int j = 0; j < 8; j++)
                    acc[i][j] = fmaf(a[i], bv[j], acc[i][j]);
        }
        __syncthreads();
    }
    float bias[8];
    *(float4*)bias     = *(const float4*)(liftb + nb + tx*8);
    *(float4*)(bias+4) = *(const float4*)(liftb + nb + tx*8 + 4);
    #pragma unroll
    for (int i = 0; i < 8; i++) {
        int m = mb + ty*8 + i;
        float* op = g_h + (size_t)m*1024 + nb + tx*8;
        *(float4*)op     = make_float4(acc[i][0]+bias[0], acc[i][1]+bias[1],
                                       acc[i][2]+bias[2], acc[i][3]+bias[3]);
        *(float4*)(op+4) = make_float4(acc[i][4]+bias[4], acc[i][5]+bias[5],
                                       acc[i][6]+bias[6], acc[i][7]+bias[7]);
    }
}

// ------------------------- per-blade layer GEMM -------------------------
__global__ void __launch_bounds__(256) layer_gemm(int l) {
    __shared__ float As[32][136];
    __shared__ float Bs[32][136];
    int kb = blockIdx.x;
    int mb = blockIdx.y << 7;
    const float* __restrict__ A = g_act + (size_t)kb * BC;
    const float* __restrict__ W = g_Wk + (size_t)(l*8 + kb) * CN * CN;
    int tid = threadIdx.x;
    int tx = tid & 15, ty = tid >> 4;
    float acc[8][8];
    #pragma unroll
    for (int i = 0; i < 8; i++)
        #pragma unroll
        for (int j = 0; j < 8; j++) acc[i][j] = 0.0f;

    for (int kt = 0; kt < 128; kt += 32) {
        #pragma unroll
        for (int e = 0; e < 4; e++) {
            int q = tid*4 + e; int row = q >> 3, c4 = q & 7;
            float4 v = *(const float4*)(A + (size_t)(mb + row)*128 + kt + c4*4);
            As[c4*4+0][row] = v.x; As[c4*4+1][row] = v.y;
            As[c4*4+2][row] = v.z; As[c4*4+3][row] = v.w;
        }
        #pragma unroll
        for (int e = 0; e < 4; e++) {
            int q = tid*4 + e; int r = q >> 5, c4 = q & 31;
            float4 v = *(const float4*)(W + (size_t)(kt + r)*128 + c4*4);
            *(float4*)&Bs[r][c4*4] = v;
        }
        __syncthreads();
        #pragma unroll
        for (int kk = 0; kk < 32; kk++) {
            float a[8], bv[8];
            *(float4*)(a)    = *(const float4*)&As[kk][ty*8];
            *(float4*)(a+4)  = *(const float4*)&As[kk][ty*8+4];
            *(float4*)(bv)   = *(const float4*)&Bs[kk][tx*8];
            *(float4*)(bv+4) = *(const float4*)&Bs[kk][tx*8+4];
            #pragma unroll
            for (int i = 0; i < 8; i++)
                #pragma unroll
                for (int j = 0; j < 8; j++)
                    acc[i][j] = fmaf(a[i], bv[j], acc[i][j]);
        }
        __syncthreads();
    }
    #pragma unroll
    for (int i = 0; i < 8; i++) {
        float* op = g_gout + (size_t)kb*BC + (size_t)(mb + ty*8 + i)*128 + tx*8;
        *(float4*)op     = make_float4(acc[i][0], acc[i][1], acc[i][2], acc[i][3]);
        *(float4*)(op+4) = make_float4(acc[i][4], acc[i][5], acc[i][6], acc[i][7]);
    }
}

// ------------------------- grade-wise RMS block reduction (128 channels per row group) ---------
__device__ __forceinline__ void grade_denom(const float* x, float* denom, float (*sred)[4], int c) {
    float v[4];
    v[0] = x[0]*x[0];
    v[1] = x[1]*x[1] + x[2]*x[2] + x[3]*x[3];
    v[2] = x[4]*x[4] + x[5]*x[5] + x[6]*x[6];
    v[3] = x[7]*x[7];
    #pragma unroll
    for (int g = 0; g < 4; g++) {
        float t = v[g];
        t += __shfl_xor_sync(0xffffffffu, t, 16);
        t += __shfl_xor_sync(0xffffffffu, t, 8);
        t += __shfl_xor_sync(0xffffffffu, t, 4);
        t += __shfl_xor_sync(0xffffffffu, t, 2);
        t += __shfl_xor_sync(0xffffffffu, t, 1);
        if ((c & 31) == 0) sred[g][c >> 5] = t;
    }
    __syncthreads();
    #pragma unroll
    for (int g = 0; g < 4; g++)
        denom[g] = sqrtf((sred[g][0]+sred[g][1]+sred[g][2]+sred[g][3]) * (1.0f/128.0f) + EPSF);
    __syncthreads();
}

__device__ __forceinline__ void ln_apply(float* x, const float* gamma, const float* denom, int c) {
    float f0 = gamma[c*4+0] / denom[0];
    float f1 = gamma[c*4+1] / denom[1];
    float f2 = gamma[c*4+2] / denom[2];
    float f3 = gamma[c*4+3] / denom[3];
    x[0] *= f0;
    x[1] *= f1; x[2] *= f1; x[3] *= f1;
    x[4] *= f2; x[5] *= f2; x[6] *= f2;
    x[7] *= f3;
}

// Mt: transposed rotor matrix base for this layer; element (j,k) for channel c at Mt[(j*8+k)*CN + c]
__device__ __forceinline__ void rot_gelu_store(const float* x, const float* __restrict__ Mt,
                                               float alpha, int b, int c) {
    float y[8] = {0,0,0,0,0,0,0,0};
    #pragma unroll
    for (int j = 0; j < 8; j++) {
        float xj = x[j];
        #pragma unroll
        for (int k = 0; k < 8; k++)
            y[k] = fmaf(xj, __ldg(Mt + (size_t)(j*8+k)*CN + c), y[k]);
    }
    float nn = EPSF;
    #pragma unroll
    for (int k = 0; k < 8; k++) nn = fmaf(y[k], y[k], nn);
    float gate = 0.5f * (1.0f + erff(alpha * sqrtf(nn) * 0.70710678118654752f));
    #pragma unroll
    for (int k = 0; k < 8; k++) g_act[(size_t)k*BC + b*128 + c] = y[k] * gate;
}

// ------------------------- input norm + layer-0 prologue -------------------------
__global__ void __launch_bounds__(256) ln_in_kernel(const float* __restrict__ in_gamma,
                                                    const float* __restrict__ ng0,
                                                    const float* __restrict__ alpha0) {
    __shared__ float sred[2][4][4];
    int row = threadIdx.x >> 7;
    int c = threadIdx.x & 127;
    int b = blockIdx.x * 2 + row;
    float x[8];
    const float* p = g_h + (size_t)(b*128 + c) * 8;
    *(float4*)x     = *(const float4*)p;
    *(float4*)(x+4) = *(const float4*)(p+4);

    float denom[4];
    grade_denom(x, denom, sred[row], c);
    ln_apply(x, in_gamma, denom, c);

    float* pr = g_res + (size_t)(b*128 + c) * 8;
    *(float4*)pr     = *(const float4*)x;
    *(float4*)(pr+4) = *(const float4*)(x+4);

    grade_denom(x, denom, sred[row], c);
    ln_apply(x, ng0, denom, c);
    rot_gelu_store(x, g_rotM, alpha0[c], b, c);
}

// ------------------------- inter-layer pointwise -------------------------
__global__ void __launch_bounds__(256) ip_kernel(const float* __restrict__ Mt_next,
                                                 const float* __restrict__ linb,
                                                 const float* __restrict__ resIn,
                                                 float* __restrict__ outI,
                                                 const float* __restrict__ gamma_next,
                                                 const float* __restrict__ alpha_next,
                                                 int final_ln) {
    __shared__ float sred[2][4][4];
    int row = threadIdx.x >> 7;
    int c = threadIdx.x & 127;
    int b = blockIdx.x * 2 + row;
    float x[8];
    #pragma unroll
    for (int k = 0; k < 8; k++)
        x[k] = g_gout[(size_t)k*BC + b*128 + c] + linb[c*8 + k];

    const float* pr = resIn + (size_t)(b*128 + c) * 8;
    float r[8];
    *(float4*)r     = *(const float4*)pr;
    *(float4*)(r+4) = *(const float4*)(pr+4);
    #pragma unroll
    for (int k = 0; k < 8; k++) x[k] += r[k];

    float* po = outI + (size_t)(b*128 + c) * 8;
    *(float4*)po     = *(const float4*)x;
    *(float4*)(po+4) = *(const float4*)(x+4);

    float denom[4];
    grade_denom(x, denom, sred[row], c);
    ln_apply(x, gamma_next, denom, c);

    if (!final_ln) {
        rot_gelu_store(x, Mt_next, alpha_next[c], b, c);
    } else {
        #pragma unroll
        for (int k = 0; k < 8; k++) g_act[(size_t)k*BC + b*128 + c] = x[k];
    }
}

// ------------------------- projection (bivector blades only) -------------------------
__global__ void __launch_bounds__(256) proj_kernel(const float* __restrict__ projW,
                                                   const float* __restrict__ projb,
                                                   float* __restrict__ out) {
    int warp = threadIdx.x >> 5, lane = threadIdx.x & 31;
    int b = blockIdx.x * 8 + warp;
    if (b >= BN) return;

    out[b*32 + lane] = 0.0f;
    __syncwarp();

    #pragma unroll
    for (int kk = 0; kk < 3; kk++) {
        int k = 4 + kk;
        float av[4];
        #pragma unroll
        for (int q = 0; q < 4; q++)
            av[q] = g_act[(size_t)k*BC + b*128 + lane + 32*q];
        #pragma unroll
        for (int o = 0; o < 4; o++) {
            float s = 0.0f;
            #pragma unroll
            for (int q = 0; q < 4; q++)
                s = fmaf(av[q], projW[(size_t)(o*128 + lane + 32*q)*8 + k], s);
            s += __shfl_xor_sync(0xffffffffu, s, 16);
            s += __shfl_xor_sync(0xffffffffu, s, 8);
            s += __shfl_xor_sync(0xffffffffu, s, 4);
            s += __shfl_xor_sync(0xffffffffu, s, 2);
            s += __shfl_xor_sync(0xffffffffu, s, 1);
            if (lane == 0) out[b*32 + o*8 + k] = s + projb[o*8 + k];
        }
    }
}

// ------------------------- launch -------------------------
extern "C" void kernel_launch(void* const* d_in, const int* in_sizes, int n_in,
                              void* d_out, int out_size) {
    const float* coords     = (const float*)d_in[0];
    const float* freq       = (const float*)d_in[1];
    const float* liftW      = (const float*)d_in[2];
    const float* liftb      = (const float*)d_in[3];
    const float* in_gamma   = (const float*)d_in[4];
    const float* norm_gamma = (const float*)d_in[5];
    const float* rotor_th   = (const float*)d_in[6];
    const float* act_alpha  = (const float*)d_in[7];
    const float* linW       = (const float*)d_in[8];
    const float* linb       = (const float*)d_in[9];
    const float* out_gamma  = (const float*)d_in[10];
    const float* projW      = (const float*)d_in[11];
    const float* projb      = (const float*)d_in[12];
    float* out = (float*)d_out;

    float* rotM_ptr;
    cudaGetSymbolAddress((void**)&rotM_ptr, g_rotM);
    float* res_ptr;
    cudaGetSymbolAddress((void**)&res_ptr, g_res);

    repack<<<(NL*8*CN*CN + 255)/256, 256>>>(linW);
    rotor_pre<<<4, 256>>>(rotor_th);
    feats_kernel<<<BN*32/256, 256>>>(coords, freq);
    lift_gemm<<<dim3(8, BN/128), 256>>>(liftW, liftb);
    ln_in_kernel<<<BN/2, 256>>>(in_gamma, norm_gamma, act_alpha);

    for (int l = 0; l < NL; l++) {
        layer_gemm<<<dim3(8, BN/128), 256>>>(l);
        const float* gnext = (l < NL-1) ? (norm_gamma + (size_t)(l+1)*CN*4) : out_gamma;
        const float* anext = (l < NL-1) ? (act_alpha + (size_t)(l+1)*CN)   : act_alpha;
        const float* resIn = (l == 0) ? res_ptr : (out + AMU_SIZE + (size_t)(l-1)*SLICE);
        ip_kernel<<<BN/2, 256>>>(rotM_ptr + (size_t)(l+1)*64*CN,
                                 linb + (size_t)l*CN*8,
                                 resIn,
                                 out + AMU_SIZE + (size_t)l*SLICE,
                                 gnext, anext, (l == NL-1) ? 1 : 0);
    }
    proj_kernel<<<BN/8, 256>>>(projW, projb, out);
}

// round 5
// speedup vs baseline: 4.2944x; 1.5005x over previous
#include <cuda_runtime.h>
#include <cuda_bf16.h>
#include <math.h>
#include <stdint.h>

#define BN 8192
#define CN 128
#define NL 8
#define BC (BN*CN)
#define SLICE (BC*8)
#define AMU_SIZE (BN*32)
#define EPSF 1e-6f
#define SA 72   // SMEM tile row stride in bf16 units (36 words == 4 mod 32 -> conflict-free)

// ------------------------- device scratch -------------------------
__device__ float g_feats[BN*160];
__device__ __nv_bfloat16 g_Wb_hi[NL*8*CN*CN];   // [l][kb][o][i]
__device__ __nv_bfloat16 g_Wb_lo[NL*8*CN*CN];
__device__ float g_rotM[NL*64*CN];              // transposed rotor matrices [l][jk][c]
__device__ float g_h[BC*8];                     // lift output interleaved
__device__ float g_res[BC*8];                   // layer-0 residual
__device__ __nv_bfloat16 g_act_hi[8*BC];        // blade-planar activations (hi)
__device__ __nv_bfloat16 g_act_lo[8*BC];        // (lo)
__device__ float g_act[8*BC];                   // final-layer fp32 activations (for proj)
__device__ float g_gout[8*BC];                  // blade-planar gemm output

__device__ const int c_blades[8] = {0,1,2,4,3,5,6,7};

__device__ __forceinline__ int cl_sign(int a, int b) {
    int s = 0; int aa = a >> 1;
    while (aa) { s += __popc(aa & b); aa >>= 1; }
    return (s & 1) ? -1 : 1;
}

__device__ __forceinline__ void mma16816(float* c, const uint32_t* a, const uint32_t* b) {
    asm volatile("mma.sync.aligned.m16n8k16.row.col.f32.bf16.bf16.f32 "
        "{%0,%1,%2,%3}, {%4,%5,%6,%7}, {%8,%9}, {%0,%1,%2,%3};"
        : "+f"(c[0]), "+f"(c[1]), "+f"(c[2]), "+f"(c[3])
        : "r"(a[0]), "r"(a[1]), "r"(a[2]), "r"(a[3]), "r"(b[0]), "r"(b[1]));
}

// ------------------------- rotor matrix precompute -------------------------
__global__ void rotor_pre(const float* __restrict__ theta) {
    int n = blockIdx.x * blockDim.x + threadIdx.x;
    if (n >= NL * CN) return;
    int l = n / CN, c = n % CN;
    const float* t = theta + n * 3;
    float ang = sqrtf(t[0]*t[0] + t[1]*t[1] + t[2]*t[2] + EPSF);
    float R[8] = {0,0,0,0,0,0,0,0};
    R[0] = cosf(ang);
    float s = sinf(ang) / ang;
    R[4] = s * t[0]; R[5] = s * t[1]; R[6] = s * t[2];
    float Rr[8];
    #pragma unroll
    for (int i = 0; i < 8; i++) Rr[i] = (i >= 4) ? -R[i] : R[i];
    float M[64];
    #pragma unroll
    for (int i = 0; i < 64; i++) M[i] = 0.0f;
    const int iv[4] = {0, 4, 5, 6};
    for (int ii = 0; ii < 4; ii++) {
        int i = iv[ii]; float Ri = R[i]; int a = c_blades[i];
        for (int j = 0; j < 8; j++) {
            int bb = c_blades[j];
            int m_mask = a ^ bb;
            float tj = Ri * (float)cl_sign(a, bb);
            for (int pp = 0; pp < 4; pp++) {
                int p = iv[pp]; int pm = c_blades[p];
                int k_mask = m_mask ^ pm;
                float s2 = (float)cl_sign(m_mask, pm);
                int k = c_blades[k_mask];
                M[j*8 + k] += tj * Rr[p] * s2;
            }
        }
    }
    float* out = g_rotM + (size_t)l*64*CN + c;
    #pragma unroll
    for (int i = 0; i < 64; i++) out[(size_t)i*CN] = M[i];
}

// ------------------------- weight repack to bf16 split [l][kb][o][i] -------------------------
__global__ void repack(const float* __restrict__ linW) {
    int n = blockIdx.x * 256 + threadIdx.x;
    if (n >= NL*8*CN*CN) return;
    int i = n & 127;
    int o = (n >> 7) & 127;
    int kb = (n >> 14) & 7;
    int l = n >> 17;
    float w = linW[(size_t)(((l*128 + o)*128 + i) * 8) + kb];
    __nv_bfloat16 hi = __float2bfloat16(w);
    g_Wb_hi[n] = hi;
    g_Wb_lo[n] = __float2bfloat16(w - __bfloat162float(hi));
}

// ------------------------- features -------------------------
__global__ void feats_kernel(const float* __restrict__ coords, const float* __restrict__ freq) {
    int gid = blockIdx.x * 256 + threadIdx.x;
    int row = gid >> 5, lane = gid & 31;
    if (row >= BN) return;
    float c0 = coords[row*4+0], c1 = coords[row*4+1];
    float c2 = coords[row*4+2], c3 = coords[row*4+3];
    float* out = g_feats + (size_t)row * 160;
    if (lane < 4) out[lane] = coords[row*4 + lane];
    #pragma unroll
    for (int f = lane; f < 64; f += 32) {
        float p = c0*freq[f] + c1*freq[64+f] + c2*freq[128+f] + c3*freq[192+f];
        out[4 + f]  = sinf(p);
        out[68 + f] = cosf(p);
    }
    if (lane < 28) out[132 + lane] = 0.0f;
}

// ------------------------- lift GEMM (fp32 SIMT) -------------------------
__global__ void __launch_bounds__(256) lift_gemm(const float* __restrict__ liftW,
                                                 const float* __restrict__ liftb) {
    __shared__ float As[32][136];
    __shared__ float Bs[32][136];
    int nb = blockIdx.x << 7, mb = blockIdx.y << 7;
    int tid = threadIdx.x;
    int tx = tid & 15, ty = tid >> 4;
    float acc[8][8];
    #pragma unroll
    for (int i = 0; i < 8; i++)
        #pragma unroll
        for (int j = 0; j < 8; j++) acc[i][j] = 0.0f;

    for (int kt = 0; kt < 160; kt += 32) {
        #pragma unroll
        for (int e = 0; e < 4; e++) {
            int q = tid*4 + e; int row = q >> 3, c4 = q & 7;
            float4 v = *(const float4*)(g_feats + (size_t)(mb + row)*160 + kt + c4*4);
            As[c4*4+0][row] = v.x; As[c4*4+1][row] = v.y;
            As[c4*4+2][row] = v.z; As[c4*4+3][row] = v.w;
        }
        #pragma unroll
        for (int e = 0; e < 4; e++) {
            int q = tid*4 + e; int r = q >> 5, c4 = q & 31;
            float4 v = make_float4(0.f, 0.f, 0.f, 0.f);
            if (kt + r < 132) v = *(const float4*)(liftW + (size_t)(kt + r)*1024 + nb + c4*4);
            *(float4*)&Bs[r][c4*4] = v;
        }
        __syncthreads();
        #pragma unroll
        for (int kk = 0; kk < 32; kk++) {
            float a[8], bv[8];
            *(float4*)(a)    = *(const float4*)&As[kk][ty*8];
            *(float4*)(a+4)  = *(const float4*)&As[kk][ty*8+4];
            *(float4*)(bv)   = *(const float4*)&Bs[kk][tx*8];
            *(float4*)(bv+4) = *(const float4*)&Bs[kk][tx*8+4];
            #pragma unroll
            for (int i = 0; i < 8; i++)
                #pragma unroll
                for (int j = 0; j < 8; j++)
                    acc[i][j] = fmaf(a[i], bv[j], acc[i][j]);
        }
        __syncthreads();
    }
    float bias[8];
    *(float4*)bias     = *(const float4*)(liftb + nb + tx*8);
    *(float4*)(bias+4) = *(const float4*)(liftb + nb + tx*8 + 4);
    #pragma unroll
    for (int i = 0; i < 8; i++) {
        int m = mb + ty*8 + i;
        float* op = g_h + (size_t)m*1024 + nb + tx*8;
        *(float4*)op     = make_float4(acc[i][0]+bias[0], acc[i][1]+bias[1],
                                       acc[i][2]+bias[2], acc[i][3]+bias[3]);
        *(float4*)(op+4) = make_float4(acc[i][4]+bias[4], acc[i][5]+bias[5],
                                       acc[i][6]+bias[6], acc[i][7]+bias[7]);
    }
}

// ------------------------- mma.sync blade GEMM -------------------------
// gout[kb][m][o] = sum_i act[kb][m][i] * W[l][kb][o][i], bf16-split x3, fp32 accum.
__global__ void __launch_bounds__(256, 2) gemm_mma(int l) {
    extern __shared__ __nv_bfloat16 sm[];
    __nv_bfloat16* sAhi = sm;
    __nv_bfloat16* sAlo = sm + 128*SA;
    __nv_bfloat16* sBhi = sm + 2*128*SA;
    __nv_bfloat16* sBlo = sm + 3*128*SA;

    int tid = threadIdx.x;
    int wid = tid >> 5, lane = tid & 31;
    int group = lane >> 2, tig = lane & 3;
    int m_warp = (wid & 3) * 32;        // 4 warps along m
    int n_warp = (wid >> 2) * 64;       // 2 warps along n

    int kb = blockIdx.x;
    int mb = blockIdx.y << 7;

    const __nv_bfloat16* Ahi = g_act_hi + (size_t)kb*BC + (size_t)mb*128;
    const __nv_bfloat16* Alo = g_act_lo + (size_t)kb*BC + (size_t)mb*128;
    const __nv_bfloat16* Bhi = g_Wb_hi + (size_t)(l*8 + kb)*CN*CN;
    const __nv_bfloat16* Blo = g_Wb_lo + (size_t)(l*8 + kb)*CN*CN;

    float acc[2][8][4];
    #pragma unroll
    for (int f = 0; f < 2; f++)
        #pragma unroll
        for (int g = 0; g < 8; g++)
            #pragma unroll
            for (int q = 0; q < 4; q++) acc[f][g][q] = 0.0f;

    #pragma unroll
    for (int chunk = 0; chunk < 2; chunk++) {
        int kc = chunk * 64;
        // load 4 tiles [128 rows x 64 cols] as uint4 (16B = 8 bf16)
        #pragma unroll
        for (int i = 0; i < 4; i++) {
            int idx = tid + 256*i;          // 0..1023
            int row = idx >> 3, ch = idx & 7;
            size_t src = (size_t)row*128 + kc + ch*8;
            int dst = row*SA + ch*8;
            *(uint4*)&sAhi[dst] = *(const uint4*)&Ahi[src];
            *(uint4*)&sAlo[dst] = *(const uint4*)&Alo[src];
            *(uint4*)&sBhi[dst] = *(const uint4*)&Bhi[src];
            *(uint4*)&sBlo[dst] = *(const uint4*)&Blo[src];
        }
        __syncthreads();

        #pragma unroll
        for (int ks = 0; ks < 4; ks++) {
            int k0 = ks * 16;
            uint32_t ahi[2][4], alo[2][4];
            #pragma unroll
            for (int f = 0; f < 2; f++) {
                int r0 = (m_warp + f*16 + group) * SA + k0 + tig*2;
                int r8 = r0 + 8*SA;
                ahi[f][0] = *(const uint32_t*)&sAhi[r0];
                ahi[f][1] = *(const uint32_t*)&sAhi[r8];
                ahi[f][2] = *(const uint32_t*)&sAhi[r0 + 8];
                ahi[f][3] = *(const uint32_t*)&sAhi[r8 + 8];
                alo[f][0] = *(const uint32_t*)&sAlo[r0];
                alo[f][1] = *(const uint32_t*)&sAlo[r8];
                alo[f][2] = *(const uint32_t*)&sAlo[r0 + 8];
                alo[f][3] = *(const uint32_t*)&sAlo[r8 + 8];
            }
            #pragma unroll
            for (int g = 0; g < 8; g++) {
                int nrow = (n_warp + g*8 + group) * SA + k0 + tig*2;
                uint32_t bhi[2], blo[2];
                bhi[0] = *(const uint32_t*)&sBhi[nrow];
                bhi[1] = *(const uint32_t*)&sBhi[nrow + 8];
                blo[0] = *(const uint32_t*)&sBlo[nrow];
                blo[1] = *(const uint32_t*)&sBlo[nrow + 8];
                #pragma unroll
                for (int f = 0; f < 2; f++) {
                    mma16816(acc[f][g], ahi[f], bhi);
                    mma16816(acc[f][g], ahi[f], blo);
                    mma16816(acc[f][g], alo[f], bhi);
                }
            }
        }
        __syncthreads();
    }

    // store: c0,c1 at (row, col..col+1); c2,c3 at (row+8, col..col+1)
    float* gbase = g_gout + (size_t)kb*BC;
    #pragma unroll
    for (int f = 0; f < 2; f++) {
        #pragma unroll
        for (int g = 0; g < 8; g++) {
            int row = mb + m_warp + f*16 + group;
            int col = n_warp + g*8 + tig*2;
            float* p = gbase + (size_t)row*128 + col;
            *(float2*)p = make_float2(acc[f][g][0], acc[f][g][1]);
            *(float2*)(p + 8*128) = make_float2(acc[f][g][2], acc[f][g][3]);
        }
    }
}

// ------------------------- pointwise helpers -------------------------
__device__ __forceinline__ void grade_denom(const float* x, float* denom, float (*sred)[4], int c) {
    float v[4];
    v[0] = x[0]*x[0];
    v[1] = x[1]*x[1] + x[2]*x[2] + x[3]*x[3];
    v[2] = x[4]*x[4] + x[5]*x[5] + x[6]*x[6];
    v[3] = x[7]*x[7];
    #pragma unroll
    for (int g = 0; g < 4; g++) {
        float t = v[g];
        t += __shfl_xor_sync(0xffffffffu, t, 16);
        t += __shfl_xor_sync(0xffffffffu, t, 8);
        t += __shfl_xor_sync(0xffffffffu, t, 4);
        t += __shfl_xor_sync(0xffffffffu, t, 2);
        t += __shfl_xor_sync(0xffffffffu, t, 1);
        if ((c & 31) == 0) sred[g][c >> 5] = t;
    }
    __syncthreads();
    #pragma unroll
    for (int g = 0; g < 4; g++)
        denom[g] = sqrtf((sred[g][0]+sred[g][1]+sred[g][2]+sred[g][3]) * (1.0f/128.0f) + EPSF);
    __syncthreads();
}

__device__ __forceinline__ void ln_apply(float* x, const float* gamma, const float* denom, int c) {
    float f0 = gamma[c*4+0] / denom[0];
    float f1 = gamma[c*4+1] / denom[1];
    float f2 = gamma[c*4+2] / denom[2];
    float f3 = gamma[c*4+3] / denom[3];
    x[0] *= f0;
    x[1] *= f1; x[2] *= f1; x[3] *= f1;
    x[4] *= f2; x[5] *= f2; x[6] *= f2;
    x[7] *= f3;
}

__device__ __forceinline__ void rot_gelu_store(const float* x, const float* __restrict__ Mt,
                                               float alpha, int b, int c) {
    float y[8] = {0,0,0,0,0,0,0,0};
    #pragma unroll
    for (int j = 0; j < 8; j++) {
        float xj = x[j];
        #pragma unroll
        for (int k = 0; k < 8; k++)
            y[k] = fmaf(xj, __ldg(Mt + (size_t)(j*8+k)*CN + c), y[k]);
    }
    float nn = EPSF;
    #pragma unroll
    for (int k = 0; k < 8; k++) nn = fmaf(y[k], y[k], nn);
    float gate = 0.5f * (1.0f + erff(alpha * sqrtf(nn) * 0.70710678118654752f));
    #pragma unroll
    for (int k = 0; k < 8; k++) {
        float v = y[k] * gate;
        __nv_bfloat16 hi = __float2bfloat16(v);
        size_t idx = (size_t)k*BC + b*128 + c;
        g_act_hi[idx] = hi;
        g_act_lo[idx] = __float2bfloat16(v - __bfloat162float(hi));
    }
}

// ------------------------- input norm + layer-0 prologue -------------------------
__global__ void __launch_bounds__(256) ln_in_kernel(const float* __restrict__ in_gamma,
                                                    const float* __restrict__ ng0,
                                                    const float* __restrict__ alpha0) {
    __shared__ float sred[2][4][4];
    int row = threadIdx.x >> 7;
    int c = threadIdx.x & 127;
    int b = blockIdx.x * 2 + row;
    float x[8];
    const float* p = g_h + (size_t)(b*128 + c) * 8;
    *(float4*)x     = *(const float4*)p;
    *(float4*)(x+4) = *(const float4*)(p+4);

    float denom[4];
    grade_denom(x, denom, sred[row], c);
    ln_apply(x, in_gamma, denom, c);

    float* pr = g_res + (size_t)(b*128 + c) * 8;
    *(float4*)pr     = *(const float4*)x;
    *(float4*)(pr+4) = *(const float4*)(x+4);

    grade_denom(x, denom, sred[row], c);
    ln_apply(x, ng0, denom, c);
    rot_gelu_store(x, g_rotM, alpha0[c], b, c);
}

// ------------------------- inter-layer pointwise -------------------------
__global__ void __launch_bounds__(256) ip_kernel(const float* __restrict__ Mt_next,
                                                 const float* __restrict__ linb,
                                                 const float* __restrict__ resIn,
                                                 float* __restrict__ outI,
                                                 const float* __restrict__ gamma_next,
                                                 const float* __restrict__ alpha_next,
                                                 int final_ln) {
    __shared__ float sred[2][4][4];
    int row = threadIdx.x >> 7;
    int c = threadIdx.x & 127;
    int b = blockIdx.x * 2 + row;
    float x[8];
    #pragma unroll
    for (int k = 0; k < 8; k++)
        x[k] = g_gout[(size_t)k*BC + b*128 + c] + linb[c*8 + k];

    const float* pr = resIn + (size_t)(b*128 + c) * 8;
    float r[8];
    *(float4*)r     = *(const float4*)pr;
    *(float4*)(r+4) = *(const float4*)(pr+4);
    #pragma unroll
    for (int k = 0; k < 8; k++) x[k] += r[k];

    float* po = outI + (size_t)(b*128 + c) * 8;
    *(float4*)po     = *(const float4*)x;
    *(float4*)(po+4) = *(const float4*)(x+4);

    float denom[4];
    grade_denom(x, denom, sred[row], c);
    ln_apply(x, gamma_next, denom, c);

    if (!final_ln) {
        rot_gelu_store(x, Mt_next, alpha_next[c], b, c);
    } else {
        #pragma unroll
        for (int k = 0; k < 8; k++) g_act[(size_t)k*BC + b*128 + c] = x[k];
    }
}

// ------------------------- projection (bivector blades only) -------------------------
__global__ void __launch_bounds__(256) proj_kernel(const float* __restrict__ projW,
                                                   const float* __restrict__ projb,
                                                   float* __restrict__ out) {
    int warp = threadIdx.x >> 5, lane = threadIdx.x & 31;
    int b = blockIdx.x * 8 + warp;
    if (b >= BN) return;

    out[b*32 + lane] = 0.0f;
    __syncwarp();

    #pragma unroll
    for (int kk = 0; kk < 3; kk++) {
        int k = 4 + kk;
        float av[4];
        #pragma unroll
        for (int q = 0; q < 4; q++)
            av[q] = g_act[(size_t)k*BC + b*128 + lane + 32*q];
        #pragma unroll
        for (int o = 0; o < 4; o++) {
            float s = 0.0f;
            #pragma unroll
            for (int q = 0; q < 4; q++)
                s = fmaf(av[q], projW[(size_t)(o*128 + lane + 32*q)*8 + k], s);
            s += __shfl_xor_sync(0xffffffffu, s, 16);
            s += __shfl_xor_sync(0xffffffffu, s, 8);
            s += __shfl_xor_sync(0xffffffffu, s, 4);
            s += __shfl_xor_sync(0xffffffffu, s, 2);
            s += __shfl_xor_sync(0xffffffffu, s, 1);
            if (lane == 0) out[b*32 + o*8 + k] = s + projb[o*8 + k];
        }
    }
}

// ------------------------- launch -------------------------
extern "C" void kernel_launch(void* const* d_in, const int* in_sizes, int n_in,
                              void* d_out, int out_size) {
    const float* coords     = (const float*)d_in[0];
    const float* freq       = (const float*)d_in[1];
    const float* liftW      = (const float*)d_in[2];
    const float* liftb      = (const float*)d_in[3];
    const float* in_gamma   = (const float*)d_in[4];
    const float* norm_gamma = (const float*)d_in[5];
    const float* rotor_th   = (const float*)d_in[6];
    const float* act_alpha  = (const float*)d_in[7];
    const float* linW       = (const float*)d_in[8];
    const float* linb       = (const float*)d_in[9];
    const float* out_gamma  = (const float*)d_in[10];
    const float* projW      = (const float*)d_in[11];
    const float* projb      = (const float*)d_in[12];
    float* out = (float*)d_out;

    float* rotM_ptr;
    cudaGetSymbolAddress((void**)&rotM_ptr, g_rotM);
    float* res_ptr;
    cudaGetSymbolAddress((void**)&res_ptr, g_res);

    const int smem_gemm = 4 * 128 * SA * (int)sizeof(__nv_bfloat16);   // 73728
    cudaFuncSetAttribute(gemm_mma, cudaFuncAttributeMaxDynamicSharedMemorySize, smem_gemm);

    repack<<<(NL*8*CN*CN + 255)/256, 256>>>(linW);
    rotor_pre<<<4, 256>>>(rotor_th);
    feats_kernel<<<BN*32/256, 256>>>(coords, freq);
    lift_gemm<<<dim3(8, BN/128), 256>>>(liftW, liftb);
    ln_in_kernel<<<BN/2, 256>>>(in_gamma, norm_gamma, act_alpha);

    for (int l = 0; l < NL; l++) {
        gemm_mma<<<dim3(8, BN/128), 256, smem_gemm>>>(l);
        const float* gnext = (l < NL-1) ? (norm_gamma + (size_t)(l+1)*CN*4) : out_gamma;
        const float* anext = (l < NL-1) ? (act_alpha + (size_t)(l+1)*CN)   : act_alpha;
        const float* resIn = (l == 0) ? res_ptr : (out + AMU_SIZE + (size_t)(l-1)*SLICE);
        ip_kernel<<<BN/2, 256>>>(rotM_ptr + (size_t)(l+1)*64*CN,
                                 linb + (size_t)l*CN*8,
                                 resIn,
                                 out + AMU_SIZE + (size_t)l*SLICE,
                                 gnext, anext, (l == NL-1) ? 1 : 0);
    }
    proj_kernel<<<BN/8, 256>>>(projW, projb, out);
}

// round 6
// speedup vs baseline: 4.6444x; 1.0815x over previous
#include <cuda_runtime.h>
#include <cuda_bf16.h>
#include <math.h>
#include <stdint.h>

#define BN 8192
#define CN 128
#define NL 8
#define BC (BN*CN)
#define SLICE (BC*8)
#define AMU_SIZE (BN*32)
#define EPSF 1e-6f
#define SA 72    // layer gemm SMEM row stride (bf16): 36 words == 4 mod 32 -> conflict-free
#define KL 160   // lift K padded (132 -> 160)
#define SAL 88   // lift SMEM row stride (bf16): 44 words == 12 mod 32 -> conflict-free

// ------------------------- device scratch -------------------------
__device__ __nv_bfloat16 g_feats_hi[BN*KL];
__device__ __nv_bfloat16 g_feats_lo[BN*KL];
__device__ __nv_bfloat16 g_LW_hi[1024*KL];      // liftW transposed [n][k]
__device__ __nv_bfloat16 g_LW_lo[1024*KL];
__device__ __nv_bfloat16 g_Wb_hi[NL*8*CN*CN];   // [l][kb][o][i]
__device__ __nv_bfloat16 g_Wb_lo[NL*8*CN*CN];
__device__ float g_rotM[NL*64*CN];              // transposed rotor matrices [l][jk][c]
__device__ float g_h[BC*8];                     // lift output interleaved
__device__ float g_res[BC*8];                   // layer-0 residual
__device__ __nv_bfloat16 g_act_hi[8*BC];        // blade-planar activations (hi)
__device__ __nv_bfloat16 g_act_lo[8*BC];        // (lo)
__device__ float g_act[8*BC];                   // final-layer fp32 activations (for proj)
__device__ float g_gout[8*BC];                  // blade-planar gemm output

__device__ const int c_blades[8] = {0,1,2,4,3,5,6,7};

__device__ __forceinline__ int cl_sign(int a, int b) {
    int s = 0; int aa = a >> 1;
    while (aa) { s += __popc(aa & b); aa >>= 1; }
    return (s & 1) ? -1 : 1;
}

__device__ __forceinline__ void mma16816(float* c, const uint32_t* a, const uint32_t* b) {
    asm volatile("mma.sync.aligned.m16n8k16.row.col.f32.bf16.bf16.f32 "
        "{%0,%1,%2,%3}, {%4,%5,%6,%7}, {%8,%9}, {%0,%1,%2,%3};"
        : "+f"(c[0]), "+f"(c[1]), "+f"(c[2]), "+f"(c[3])
        : "r"(a[0]), "r"(a[1]), "r"(a[2]), "r"(a[3]), "r"(b[0]), "r"(b[1]));
}

// ------------------------- rotor matrix precompute -------------------------
__global__ void rotor_pre(const float* __restrict__ theta) {
    int n = blockIdx.x * blockDim.x + threadIdx.x;
    if (n >= NL * CN) return;
    int l = n / CN, c = n % CN;
    const float* t = theta + n * 3;
    float ang = sqrtf(t[0]*t[0] + t[1]*t[1] + t[2]*t[2] + EPSF);
    float R[8] = {0,0,0,0,0,0,0,0};
    R[0] = cosf(ang);
    float s = sinf(ang) / ang;
    R[4] = s * t[0]; R[5] = s * t[1]; R[6] = s * t[2];
    float Rr[8];
    #pragma unroll
    for (int i = 0; i < 8; i++) Rr[i] = (i >= 4) ? -R[i] : R[i];
    float M[64];
    #pragma unroll
    for (int i = 0; i < 64; i++) M[i] = 0.0f;
    const int iv[4] = {0, 4, 5, 6};
    for (int ii = 0; ii < 4; ii++) {
        int i = iv[ii]; float Ri = R[i]; int a = c_blades[i];
        for (int j = 0; j < 8; j++) {
            int bb = c_blades[j];
            int m_mask = a ^ bb;
            float tj = Ri * (float)cl_sign(a, bb);
            for (int pp = 0; pp < 4; pp++) {
                int p = iv[pp]; int pm = c_blades[p];
                int k_mask = m_mask ^ pm;
                float s2 = (float)cl_sign(m_mask, pm);
                int k = c_blades[k_mask];
                M[j*8 + k] += tj * Rr[p] * s2;
            }
        }
    }
    float* out = g_rotM + (size_t)l*64*CN + c;
    #pragma unroll
    for (int i = 0; i < 64; i++) out[(size_t)i*CN] = M[i];
}

// ------------------------- weight repack to bf16 split [l][kb][o][i] -------------------------
__global__ void repack(const float* __restrict__ linW) {
    int n = blockIdx.x * 256 + threadIdx.x;
    if (n >= NL*8*CN*CN) return;
    int i = n & 127;
    int o = (n >> 7) & 127;
    int kb = (n >> 14) & 7;
    int l = n >> 17;
    float w = linW[(size_t)(((l*128 + o)*128 + i) * 8) + kb];
    __nv_bfloat16 hi = __float2bfloat16(w);
    g_Wb_hi[n] = hi;
    g_Wb_lo[n] = __float2bfloat16(w - __bfloat162float(hi));
}

// ------------------------- lift weight repack: liftW[k][n] -> [n][k] bf16 split, k padded -------
__global__ void repack_lift(const float* __restrict__ liftW) {
    int n = blockIdx.x * 256 + threadIdx.x;
    if (n >= 1024*KL) return;
    int k = n % KL;
    int o = n / KL;
    float w = (k < 132) ? liftW[(size_t)k*1024 + o] : 0.0f;
    __nv_bfloat16 hi = __float2bfloat16(w);
    g_LW_hi[n] = hi;
    g_LW_lo[n] = __float2bfloat16(w - __bfloat162float(hi));
}

// ------------------------- features (bf16 hi/lo planes) -------------------------
__global__ void feats_kernel(const float* __restrict__ coords, const float* __restrict__ freq) {
    int gid = blockIdx.x * 256 + threadIdx.x;
    int row = gid >> 5, lane = gid & 31;
    if (row >= BN) return;
    float c0 = coords[row*4+0], c1 = coords[row*4+1];
    float c2 = coords[row*4+2], c3 = coords[row*4+3];
    __nv_bfloat16* oh = g_feats_hi + (size_t)row * KL;
    __nv_bfloat16* ol = g_feats_lo + (size_t)row * KL;
    if (lane < 4) {
        float v = coords[row*4 + lane];
        __nv_bfloat16 hi = __float2bfloat16(v);
        oh[lane] = hi; ol[lane] = __float2bfloat16(v - __bfloat162float(hi));
    }
    #pragma unroll
    for (int f = lane; f < 64; f += 32) {
        float p = c0*freq[f] + c1*freq[64+f] + c2*freq[128+f] + c3*freq[192+f];
        float sv = sinf(p), cv = cosf(p);
        __nv_bfloat16 sh = __float2bfloat16(sv);
        __nv_bfloat16 ch = __float2bfloat16(cv);
        oh[4 + f]  = sh; ol[4 + f]  = __float2bfloat16(sv - __bfloat162float(sh));
        oh[68 + f] = ch; ol[68 + f] = __float2bfloat16(cv - __bfloat162float(ch));
    }
    if (lane < 28) {
        oh[132 + lane] = __float2bfloat16(0.0f);
        ol[132 + lane] = __float2bfloat16(0.0f);
    }
}

// ------------------------- lift GEMM via mma: h[m][n] = feats[m][:].liftW[:][n] + b[n] ----------
__global__ void __launch_bounds__(256, 2) lift_mma(const float* __restrict__ liftb) {
    extern __shared__ __nv_bfloat16 sm[];
    __nv_bfloat16* sAhi = sm;
    __nv_bfloat16* sAlo = sm + 128*SAL;
    __nv_bfloat16* sBhi = sm + 2*128*SAL;
    __nv_bfloat16* sBlo = sm + 3*128*SAL;

    int tid = threadIdx.x;
    int wid = tid >> 5, lane = tid & 31;
    int group = lane >> 2, tig = lane & 3;
    int m_warp = (wid & 3) * 32;
    int n_warp = (wid >> 2) * 64;

    int nb = blockIdx.x << 7;
    int mb = blockIdx.y << 7;

    const __nv_bfloat16* Ahi = g_feats_hi + (size_t)mb*KL;
    const __nv_bfloat16* Alo = g_feats_lo + (size_t)mb*KL;
    const __nv_bfloat16* Bhi = g_LW_hi + (size_t)nb*KL;
    const __nv_bfloat16* Blo = g_LW_lo + (size_t)nb*KL;

    float acc[2][8][4];
    #pragma unroll
    for (int f = 0; f < 2; f++)
        #pragma unroll
        for (int g = 0; g < 8; g++)
            #pragma unroll
            for (int q = 0; q < 4; q++) acc[f][g][q] = 0.0f;

    #pragma unroll
    for (int chunk = 0; chunk < 2; chunk++) {
        int kc = chunk * 80;
        // 128 rows x 80 cols per tile = 1280 uint4 per tile
        #pragma unroll
        for (int i = 0; i < 5; i++) {
            int idx = tid + 256*i;          // 0..1279
            int row = idx / 10, ch = idx % 10;
            size_t src = (size_t)row*KL + kc + ch*8;
            int dst = row*SAL + ch*8;
            *(uint4*)&sAhi[dst] = *(const uint4*)&Ahi[src];
            *(uint4*)&sAlo[dst] = *(const uint4*)&Alo[src];
            *(uint4*)&sBhi[dst] = *(const uint4*)&Bhi[src];
            *(uint4*)&sBlo[dst] = *(const uint4*)&Blo[src];
        }
        __syncthreads();

        #pragma unroll
        for (int ks = 0; ks < 5; ks++) {
            int k0 = ks * 16;
            uint32_t ahi[2][4], alo[2][4];
            #pragma unroll
            for (int f = 0; f < 2; f++) {
                int r0 = (m_warp + f*16 + group) * SAL + k0 + tig*2;
                int r8 = r0 + 8*SAL;
                ahi[f][0] = *(const uint32_t*)&sAhi[r0];
                ahi[f][1] = *(const uint32_t*)&sAhi[r8];
                ahi[f][2] = *(const uint32_t*)&sAhi[r0 + 8];
                ahi[f][3] = *(const uint32_t*)&sAhi[r8 + 8];
                alo[f][0] = *(const uint32_t*)&sAlo[r0];
                alo[f][1] = *(const uint32_t*)&sAlo[r8];
                alo[f][2] = *(const uint32_t*)&sAlo[r0 + 8];
                alo[f][3] = *(const uint32_t*)&sAlo[r8 + 8];
            }
            #pragma unroll
            for (int g = 0; g < 8; g++) {
                int nrow = (n_warp + g*8 + group) * SAL + k0 + tig*2;
                uint32_t bhi[2], blo[2];
                bhi[0] = *(const uint32_t*)&sBhi[nrow];
                bhi[1] = *(const uint32_t*)&sBhi[nrow + 8];
                blo[0] = *(const uint32_t*)&sBlo[nrow];
                blo[1] = *(const uint32_t*)&sBlo[nrow + 8];
                #pragma unroll
                for (int f = 0; f < 2; f++) {
                    mma16816(acc[f][g], ahi[f], bhi);
                    mma16816(acc[f][g], ahi[f], blo);
                    mma16816(acc[f][g], alo[f], bhi);
                }
            }
        }
        __syncthreads();
    }

    #pragma unroll
    for (int f = 0; f < 2; f++) {
        #pragma unroll
        for (int g = 0; g < 8; g++) {
            int row = mb + m_warp + f*16 + group;
            int col = nb + n_warp + g*8 + tig*2;
            float b0 = liftb[col], b1 = liftb[col+1];
            float* p = g_h + (size_t)row*1024 + col;
            *(float2*)p = make_float2(acc[f][g][0] + b0, acc[f][g][1] + b1);
            *(float2*)(p + 8*1024) = make_float2(acc[f][g][2] + b0, acc[f][g][3] + b1);
        }
    }
}

// ------------------------- mma.sync blade GEMM -------------------------
__global__ void __launch_bounds__(256, 2) gemm_mma(int l) {
    extern __shared__ __nv_bfloat16 sm[];
    __nv_bfloat16* sAhi = sm;
    __nv_bfloat16* sAlo = sm + 128*SA;
    __nv_bfloat16* sBhi = sm + 2*128*SA;
    __nv_bfloat16* sBlo = sm + 3*128*SA;

    int tid = threadIdx.x;
    int wid = tid >> 5, lane = tid & 31;
    int group = lane >> 2, tig = lane & 3;
    int m_warp = (wid & 3) * 32;
    int n_warp = (wid >> 2) * 64;

    int kb = blockIdx.x;
    int mb = blockIdx.y << 7;

    const __nv_bfloat16* Ahi = g_act_hi + (size_t)kb*BC + (size_t)mb*128;
    const __nv_bfloat16* Alo = g_act_lo + (size_t)kb*BC + (size_t)mb*128;
    const __nv_bfloat16* Bhi = g_Wb_hi + (size_t)(l*8 + kb)*CN*CN;
    const __nv_bfloat16* Blo = g_Wb_lo + (size_t)(l*8 + kb)*CN*CN;

    float acc[2][8][4];
    #pragma unroll
    for (int f = 0; f < 2; f++)
        #pragma unroll
        for (int g = 0; g < 8; g++)
            #pragma unroll
            for (int q = 0; q < 4; q++) acc[f][g][q] = 0.0f;

    #pragma unroll
    for (int chunk = 0; chunk < 2; chunk++) {
        int kc = chunk * 64;
        #pragma unroll
        for (int i = 0; i < 4; i++) {
            int idx = tid + 256*i;
            int row = idx >> 3, ch = idx & 7;
            size_t src = (size_t)row*128 + kc + ch*8;
            int dst = row*SA + ch*8;
            *(uint4*)&sAhi[dst] = *(const uint4*)&Ahi[src];
            *(uint4*)&sAlo[dst] = *(const uint4*)&Alo[src];
            *(uint4*)&sBhi[dst] = *(const uint4*)&Bhi[src];
            *(uint4*)&sBlo[dst] = *(const uint4*)&Blo[src];
        }
        __syncthreads();

        #pragma unroll
        for (int ks = 0; ks < 4; ks++) {
            int k0 = ks * 16;
            uint32_t ahi[2][4], alo[2][4];
            #pragma unroll
            for (int f = 0; f < 2; f++) {
                int r0 = (m_warp + f*16 + group) * SA + k0 + tig*2;
                int r8 = r0 + 8*SA;
                ahi[f][0] = *(const uint32_t*)&sAhi[r0];
                ahi[f][1] = *(const uint32_t*)&sAhi[r8];
                ahi[f][2] = *(const uint32_t*)&sAhi[r0 + 8];
                ahi[f][3] = *(const uint32_t*)&sAhi[r8 + 8];
                alo[f][0] = *(const uint32_t*)&sAlo[r0];
                alo[f][1] = *(const uint32_t*)&sAlo[r8];
                alo[f][2] = *(const uint32_t*)&sAlo[r0 + 8];
                alo[f][3] = *(const uint32_t*)&sAlo[r8 + 8];
            }
            #pragma unroll
            for (int g = 0; g < 8; g++) {
                int nrow = (n_warp + g*8 + group) * SA + k0 + tig*2;
                uint32_t bhi[2], blo[2];
                bhi[0] = *(const uint32_t*)&sBhi[nrow];
                bhi[1] = *(const uint32_t*)&sBhi[nrow + 8];
                blo[0] = *(const uint32_t*)&sBlo[nrow];
                blo[1] = *(const uint32_t*)&sBlo[nrow + 8];
                #pragma unroll
                for (int f = 0; f < 2; f++) {
                    mma16816(acc[f][g], ahi[f], bhi);
                    mma16816(acc[f][g], ahi[f], blo);
                    mma16816(acc[f][g], alo[f], bhi);
                }
            }
        }
        __syncthreads();
    }

    float* gbase = g_gout + (size_t)kb*BC;
    #pragma unroll
    for (int f = 0; f < 2; f++) {
        #pragma unroll
        for (int g = 0; g < 8; g++) {
            int row = mb + m_warp + f*16 + group;
            int col = n_warp + g*8 + tig*2;
            float* p = gbase + (size_t)row*128 + col;
            *(float2*)p = make_float2(acc[f][g][0], acc[f][g][1]);
            *(float2*)(p + 8*128) = make_float2(acc[f][g][2], acc[f][g][3]);
        }
    }
}

// ------------------------- pointwise helpers -------------------------
__device__ __forceinline__ void grade_denom(const float* x, float* denom, float (*sred)[4], int c) {
    float v[4];
    v[0] = x[0]*x[0];
    v[1] = x[1]*x[1] + x[2]*x[2] + x[3]*x[3];
    v[2] = x[4]*x[4] + x[5]*x[5] + x[6]*x[6];
    v[3] = x[7]*x[7];
    #pragma unroll
    for (int g = 0; g < 4; g++) {
        float t = v[g];
        t += __shfl_xor_sync(0xffffffffu, t, 16);
        t += __shfl_xor_sync(0xffffffffu, t, 8);
        t += __shfl_xor_sync(0xffffffffu, t, 4);
        t += __shfl_xor_sync(0xffffffffu, t, 2);
        t += __shfl_xor_sync(0xffffffffu, t, 1);
        if ((c & 31) == 0) sred[g][c >> 5] = t;
    }
    __syncthreads();
    #pragma unroll
    for (int g = 0; g < 4; g++)
        denom[g] = sqrtf((sred[g][0]+sred[g][1]+sred[g][2]+sred[g][3]) * (1.0f/128.0f) + EPSF);
    __syncthreads();
}

__device__ __forceinline__ void ln_apply(float* x, const float* gamma, const float* denom, int c) {
    float f0 = gamma[c*4+0] / denom[0];
    float f1 = gamma[c*4+1] / denom[1];
    float f2 = gamma[c*4+2] / denom[2];
    float f3 = gamma[c*4+3] / denom[3];
    x[0] *= f0;
    x[1] *= f1; x[2] *= f1; x[3] *= f1;
    x[4] *= f2; x[5] *= f2; x[6] *= f2;
    x[7] *= f3;
}

__device__ __forceinline__ void rot_gelu_store(const float* x, const float* __restrict__ Mt,
                                               float alpha, int b, int c) {
    float y[8] = {0,0,0,0,0,0,0,0};
    #pragma unroll
    for (int j = 0; j < 8; j++) {
        float xj = x[j];
        #pragma unroll
        for (int k = 0; k < 8; k++)
            y[k] = fmaf(xj, __ldg(Mt + (size_t)(j*8+k)*CN + c), y[k]);
    }
    float nn = EPSF;
    #pragma unroll
    for (int k = 0; k < 8; k++) nn = fmaf(y[k], y[k], nn);
    float gate = 0.5f * (1.0f + erff(alpha * sqrtf(nn) * 0.70710678118654752f));
    #pragma unroll
    for (int k = 0; k < 8; k++) {
        float v = y[k] * gate;
        __nv_bfloat16 hi = __float2bfloat16(v);
        size_t idx = (size_t)k*BC + b*128 + c;
        g_act_hi[idx] = hi;
        g_act_lo[idx] = __float2bfloat16(v - __bfloat162float(hi));
    }
}

// ------------------------- input norm + layer-0 prologue -------------------------
__global__ void __launch_bounds__(256) ln_in_kernel(const float* __restrict__ in_gamma,
                                                    const float* __restrict__ ng0,
                                                    const float* __restrict__ alpha0) {
    __shared__ float sred[2][4][4];
    int row = threadIdx.x >> 7;
    int c = threadIdx.x & 127;
    int b = blockIdx.x * 2 + row;
    float x[8];
    const float* p = g_h + (size_t)(b*128 + c) * 8;
    *(float4*)x     = *(const float4*)p;
    *(float4*)(x+4) = *(const float4*)(p+4);

    float denom[4];
    grade_denom(x, denom, sred[row], c);
    ln_apply(x, in_gamma, denom, c);

    float* pr = g_res + (size_t)(b*128 + c) * 8;
    *(float4*)pr     = *(const float4*)x;
    *(float4*)(pr+4) = *(const float4*)(x+4);

    grade_denom(x, denom, sred[row], c);
    ln_apply(x, ng0, denom, c);
    rot_gelu_store(x, g_rotM, alpha0[c], b, c);
}

// ------------------------- inter-layer pointwise -------------------------
__global__ void __launch_bounds__(256) ip_kernel(const float* __restrict__ Mt_next,
                                                 const float* __restrict__ linb,
                                                 const float* __restrict__ resIn,
                                                 float* __restrict__ outI,
                                                 const float* __restrict__ gamma_next,
                                                 const float* __restrict__ alpha_next,
                                                 int final_ln) {
    __shared__ float sred[2][4][4];
    int row = threadIdx.x >> 7;
    int c = threadIdx.x & 127;
    int b = blockIdx.x * 2 + row;
    float x[8];
    #pragma unroll
    for (int k = 0; k < 8; k++)
        x[k] = g_gout[(size_t)k*BC + b*128 + c] + linb[c*8 + k];

    const float* pr = resIn + (size_t)(b*128 + c) * 8;
    float r[8];
    *(float4*)r     = *(const float4*)pr;
    *(float4*)(r+4) = *(const float4*)(pr+4);
    #pragma unroll
    for (int k = 0; k < 8; k++) x[k] += r[k];

    float* po = outI + (size_t)(b*128 + c) * 8;
    *(float4*)po     = *(const float4*)x;
    *(float4*)(po+4) = *(const float4*)(x+4);

    float denom[4];
    grade_denom(x, denom, sred[row], c);
    ln_apply(x, gamma_next, denom, c);

    if (!final_ln) {
        rot_gelu_store(x, Mt_next, alpha_next[c], b, c);
    } else {
        #pragma unroll
        for (int k = 0; k < 8; k++) g_act[(size_t)k*BC + b*128 + c] = x[k];
    }
}

// ------------------------- projection (bivector blades only) -------------------------
__global__ void __launch_bounds__(256) proj_kernel(const float* __restrict__ projW,
                                                   const float* __restrict__ projb,
                                                   float* __restrict__ out) {
    int warp = threadIdx.x >> 5, lane = threadIdx.x & 31;
    int b = blockIdx.x * 8 + warp;
    if (b >= BN) return;

    out[b*32 + lane] = 0.0f;
    __syncwarp();

    #pragma unroll
    for (int kk = 0; kk < 3; kk++) {
        int k = 4 + kk;
        float av[4];
        #pragma unroll
        for (int q = 0; q < 4; q++)
            av[q] = g_act[(size_t)k*BC + b*128 + lane + 32*q];
        #pragma unroll
        for (int o = 0; o < 4; o++) {
            float s = 0.0f;
            #pragma unroll
            for (int q = 0; q < 4; q++)
                s = fmaf(av[q], projW[(size_t)(o*128 + lane + 32*q)*8 + k], s);
            s += __shfl_xor_sync(0xffffffffu, s, 16);
            s += __shfl_xor_sync(0xffffffffu, s, 8);
            s += __shfl_xor_sync(0xffffffffu, s, 4);
            s += __shfl_xor_sync(0xffffffffu, s, 2);
            s += __shfl_xor_sync(0xffffffffu, s, 1);
            if (lane == 0) out[b*32 + o*8 + k] = s + projb[o*8 + k];
        }
    }
}

// ------------------------- launch -------------------------
extern "C" void kernel_launch(void* const* d_in, const int* in_sizes, int n_in,
                              void* d_out, int out_size) {
    const float* coords     = (const float*)d_in[0];
    const float* freq       = (const float*)d_in[1];
    const float* liftW      = (const float*)d_in[2];
    const float* liftb      = (const float*)d_in[3];
    const float* in_gamma   = (const float*)d_in[4];
    const float* norm_gamma = (const float*)d_in[5];
    const float* rotor_th   = (const float*)d_in[6];
    const float* act_alpha  = (const float*)d_in[7];
    const float* linW       = (const float*)d_in[8];
    const float* linb       = (const float*)d_in[9];
    const float* out_gamma  = (const float*)d_in[10];
    const float* projW      = (const float*)d_in[11];
    const float* projb      = (const float*)d_in[12];
    float* out = (float*)d_out;

    float* rotM_ptr;
    cudaGetSymbolAddress((void**)&rotM_ptr, g_rotM);
    float* res_ptr;
    cudaGetSymbolAddress((void**)&res_ptr, g_res);

    const int smem_gemm = 4 * 128 * SA * (int)sizeof(__nv_bfloat16);    // 73728
    const int smem_lift = 4 * 128 * SAL * (int)sizeof(__nv_bfloat16);   // 90112
    cudaFuncSetAttribute(gemm_mma, cudaFuncAttributeMaxDynamicSharedMemorySize, smem_gemm);
    cudaFuncSetAttribute(lift_mma, cudaFuncAttributeMaxDynamicSharedMemorySize, smem_lift);

    repack<<<(NL*8*CN*CN + 255)/256, 256>>>(linW);
    repack_lift<<<(1024*KL + 255)/256, 256>>>(liftW);
    rotor_pre<<<4, 256>>>(rotor_th);
    feats_kernel<<<BN*32/256, 256>>>(coords, freq);
    lift_mma<<<dim3(8, BN/128), 256, smem_lift>>>(liftb);
    ln_in_kernel<<<BN/2, 256>>>(in_gamma, norm_gamma, act_alpha);

    for (int l = 0; l < NL; l++) {
        gemm_mma<<<dim3(8, BN/128), 256, smem_gemm>>>(l);
        const float* gnext = (l < NL-1) ? (norm_gamma + (size_t)(l+1)*CN*4) : out_gamma;
        const float* anext = (l < NL-1) ? (act_alpha + (size_t)(l+1)*CN)   : act_alpha;
        const float* resIn = (l == 0) ? res_ptr : (out + AMU_SIZE + (size_t)(l-1)*SLICE);
        ip_kernel<<<BN/2, 256>>>(rotM_ptr + (size_t)(l+1)*64*CN,
                                 linb + (size_t)l*CN*8,
                                 resIn,
                                 out + AMU_SIZE + (size_t)l*SLICE,
                                 gnext, anext, (l == NL-1) ? 1 : 0);
    }
    proj_kernel<<<BN/8, 256>>>(projW, projb, out);
}